// round 12
// baseline (speedup 1.0000x reference)
#include <cuda_runtime.h>
#include <cuda_fp16.h>
#include <math.h>
#include <stdint.h>

// Problem constants
#define BSZ   2048
#define TT    96
#define DIN   64
#define HH    256
#define KSEG  20

#define NCTA     128
#define NTHREADS 512

// staging: pitch-144 tiles of 128 rows x 64 k (bf16) = 18432 B each
#define PITCH    144
#define A_STG    18432
#define STAGE_AB (2 * A_STG)              // gemm0 stage: A + B
#define OFF_B    A_STG
// gemm0: 2 buffers of (A+B); gemm1: 3 buffers of A-only (fits in same region)
#define STG_REGION (2 * STAGE_AB)         // 73728
// persistent W1 slice: 128 rows x 512 k, pitch 1040 (1024 data + 16 pad)
#define W1_PITCH 1040
#define WB_OFF   STG_REGION               // 73728
#define SMEM_REQ (WB_OFF + 128 * W1_PITCH + 64)   // 206912 (< 227KB)

// ---------------- device scratch ----------------
__device__ __half g_x[BSZ * TT * DIN];
__device__ __half g_W0[1024 * 320];   // gate-interleaved n'=4h+g, K-major
__device__ __half g_W1[1024 * 512];
__device__ float g_b0[1024];
__device__ float g_b1[1024];
__device__ float g_Wp[21 * 512];
__device__ float g_pb[21];
__device__ float g_c0[BSZ * HH];
__device__ float g_c1[BSZ * HH];
// ping-pong h state: [b][0:256]=h0, [256:512]=h1
__device__ __half g_hb0[BSZ * 512];
__device__ __half g_hb1[BSZ * 512];
// grid barrier state (monotone generation -> replay-safe)
__device__ unsigned g_count = 0;
__device__ unsigned g_gen   = 0;

// ---------------- helpers ----------------
__device__ __forceinline__ uint32_t smem_u32(const void* p) {
    uint32_t a;
    asm("{ .reg .u64 t; cvta.to.shared.u64 t, %1; cvt.u32.u64 %0, t; }" : "=r"(a) : "l"(p));
    return a;
}
__device__ __forceinline__ void cp16(uint32_t dst, const void* src) {
    asm volatile("cp.async.cg.shared.global [%0], [%1], 16;" :: "r"(dst), "l"(src));
}
__device__ __forceinline__ void ldm_x4(uint32_t* r, uint32_t addr) {
    asm volatile("ldmatrix.sync.aligned.m8n8.x4.shared.b16 {%0,%1,%2,%3}, [%4];"
        : "=r"(r[0]), "=r"(r[1]), "=r"(r[2]), "=r"(r[3]) : "r"(addr));
}
__device__ __forceinline__ void mma_fp16(float* d, const uint32_t* a, const uint32_t* b) {
    asm volatile(
        "mma.sync.aligned.m16n8k16.row.col.f32.f16.f16.f32 "
        "{%0,%1,%2,%3}, {%4,%5,%6,%7}, {%8,%9}, {%0,%1,%2,%3};"
        : "+f"(d[0]), "+f"(d[1]), "+f"(d[2]), "+f"(d[3])
        : "r"(a[0]), "r"(a[1]), "r"(a[2]), "r"(a[3]), "r"(b[0]), "r"(b[1]));
}
__device__ __forceinline__ float fsig(float x)  { return 1.f / (1.f + __expf(-x)); }
__device__ __forceinline__ float ftanh(float x) { return 2.f / (1.f + __expf(-2.f * x)) - 1.f; }
__device__ __forceinline__ float softplusf(float x) {
    return fmaxf(x, 0.f) + log1pf(expf(-fabsf(x)));
}

// grid-wide barrier: all NCTA CTAs resident by construction
__device__ __forceinline__ void grid_bar() {
    __syncthreads();
    if (threadIdx.x == 0) {
        unsigned my = *((volatile unsigned*)&g_gen);
        __threadfence();
        unsigned old = atomicAdd(&g_count, 1);
        if (old == NCTA - 1) {
            atomicExch(&g_count, 0);
            __threadfence();
            atomicAdd(&g_gen, 1);
        } else {
            while (*((volatile unsigned*)&g_gen) == my) __nanosleep(32);
        }
        __threadfence();
    }
    __syncthreads();
}

// ---------------- init kernels ----------------
__global__ void zero_state(float* out) {
    int i = blockIdx.x * blockDim.x + threadIdx.x;
    if (i < BSZ * 512) {
        __half z = __float2half(0.f);
        g_hb0[i] = z; g_hb1[i] = z;
    }
    if (i < BSZ * HH) { g_c0[i] = 0.f; g_c1[i] = 0.f; }
    if (i == 0) out[0] = 0.f;
}

__global__ void presplit_x(const float* __restrict__ train) {
    int i = blockIdx.x * blockDim.x + threadIdx.x;
    if (i < BSZ * TT * DIN) g_x[i] = __float2half(train[i]);
}

__global__ void build_weights(
    const float* __restrict__ Wih0, const float* __restrict__ Whh0,
    const float* __restrict__ Wih1, const float* __restrict__ Whh1,
    const float* __restrict__ bih0, const float* __restrict__ bhh0,
    const float* __restrict__ bih1, const float* __restrict__ bhh1,
    const float* __restrict__ Wpb,  const float* __restrict__ bpb,
    const float* __restrict__ Wpg,  const float* __restrict__ bpg)
{
    int i = blockIdx.x * blockDim.x + threadIdx.x;
    if (i < 1024 * 320) {
        int np = i / 320, k = i % 320;
        int n = (np & 3) * 256 + (np >> 2);               // gate-interleave
        float v = (k < 64) ? Wih0[n * 64 + k] : Whh0[n * 256 + (k - 64)];
        g_W0[i] = __float2half(v);
    }
    if (i < 1024 * 512) {
        int np = i / 512, k = i % 512;
        int n = (np & 3) * 256 + (np >> 2);
        float v = (k < 256) ? Wih1[n * 256 + k] : Whh1[n * 256 + (k - 256)];
        g_W1[i] = __float2half(v);
    }
    if (i < 21 * 512) {
        int m = i / 512, k = i % 512;
        int src = 2 * (k & 255) + (k >> 8);               // hp[2j+l] = hcat[j+256l]
        g_Wp[i] = (m == 0) ? Wpb[src] : Wpg[(m - 1) * 512 + src];
    }
    if (i < 1024) {
        int n = (i & 3) * 256 + (i >> 2);
        g_b0[i] = bih0[n] + bhh0[n];
        g_b1[i] = bih1[n] + bhh1[n];
    }
    if (i < 21) g_pb[i] = (i == 0) ? bpb[0] : bpg[i - 1];
}

// ---------------- shared LSTM epilogue ----------------
// acc[i][j]: c0,c1=(m=g, n=2t,2t+1), c2,c3=(m=g+8, same n) at
// (m = wm*32+i*16, n' = wn*32+j*8). lane^1 shuffle reassembles gate quads.
template <int MODE>
__device__ __forceinline__ void lstm_epilogue(
    float acc[2][4][4], int row0, int col0,
    const float* __restrict__ bias, float* __restrict__ cbuf,
    __half* __restrict__ hB)
{
    const int lane = threadIdx.x & 31, warp = threadIdx.x >> 5;
    const int wm = warp >> 2, wn = warp & 3;
    const int g = lane >> 2, tq = lane & 3;
    const bool ev = (tq & 1) == 0;
    const int mrow = row0 + wm * 32 + g + (ev ? 0 : 8);
    __half* hout = hB + (MODE == 0 ? 0 : 256);
#pragma unroll
    for (int i = 0; i < 2; i++) {
        const int m = mrow + i * 16;
#pragma unroll
        for (int j = 0; j < 4; j++) {
            float* a = acc[i][j];
            float s0 = ev ? a[2] : a[0];
            float s1 = ev ? a[3] : a[1];
            float r0 = __shfl_xor_sync(0xFFFFFFFFu, s0, 1);
            float r1 = __shfl_xor_sync(0xFFFFFFFFu, s1, 1);
            float zi = ev ? a[0] : r0;
            float zf = ev ? a[1] : r1;
            float zg = ev ? r0 : a[2];
            float zo = ev ? r1 : a[3];
            int ul = wn * 8 + j * 2 + (tq >> 1);
            float4 bz = *(const float4*)(bias + col0 + 4 * ul);
            int ug = (col0 >> 2) + ul;
            zi += bz.x; zf += bz.y; zg += bz.z; zo += bz.w;
            float cold = cbuf[(size_t)m * HH + ug];
            float c2 = fsig(zf) * cold + fsig(zi) * ftanh(zg);
            float hv = fsig(zo) * ftanh(c2);
            cbuf[(size_t)m * HH + ug] = c2;
            hout[(size_t)m * 512 + ug] = __float2half(hv);
        }
    }
}

// ---------------- gemm0: z=[x_t|h0_prev]@W0'^T + b0 -> h0,c0 (K=320) ----------
__device__ __forceinline__ void gemm0_tile(
    uint32_t AB, int row0, int col0, int t,
    const __half* __restrict__ hA, __half* __restrict__ hB)
{
    constexpr int S = 5;
    const int tid = threadIdx.x;
    const int lane = tid & 31, warp = tid >> 5;
    const int wm = warp >> 2, wn = warp & 3;
    const __half* xp = g_x + t * 64;

    float acc[2][4][4];
#pragma unroll
    for (int i = 0; i < 2; i++)
#pragma unroll
        for (int j = 0; j < 4; j++)
#pragma unroll
            for (int r = 0; r < 4; r++) acc[i][j][r] = 0.f;

    auto stage_load = [&](int s) {
        const uint32_t bb = AB + (uint32_t)(s & 1) * STAGE_AB;
        const __half* ah;
        int lda, koff;
        if (s == 0) { ah = xp; lda = TT * DIN; koff = 0; }
        else        { ah = hA; lda = 512;      koff = (s - 1) * 64; }
#pragma unroll
        for (int rr = 0; rr < 2; rr++) {
            int pos = rr * NTHREADS + tid;
            int row = pos >> 3, c = pos & 7;
            cp16(bb + row * PITCH + c * 16,
                 ah + (size_t)(row0 + row) * lda + koff + c * 8);
        }
#pragma unroll
        for (int rr = 0; rr < 2; rr++) {
            int pos = rr * NTHREADS + tid;
            int row = pos >> 3, c = pos & 7;
            cp16(bb + OFF_B + row * PITCH + c * 16,
                 g_W0 + (size_t)(col0 + row) * 320 + s * 64 + c * 8);
        }
        asm volatile("cp.async.commit_group;");
    };

    auto compute = [&](int s) {
        const uint32_t base = AB + (uint32_t)(s & 1) * STAGE_AB;
#pragma unroll
        for (int kk = 0; kk < 64; kk += 16) {
            uint32_t af[2][4], bf[2][4];
#pragma unroll
            for (int i = 0; i < 2; i++) {
                uint32_t row = wm * 32 + i * 16 + (lane & 15);
                uint32_t cb = (kk + ((lane >> 4) << 3)) * 2;
                ldm_x4(af[i], base + row * PITCH + cb);
            }
#pragma unroll
            for (int jp = 0; jp < 2; jp++) {
                uint32_t row = wn * 32 + jp * 16 + (lane & 7) + ((lane >> 4) << 3);
                uint32_t cb = (kk + (((lane >> 3) & 1) << 3)) * 2;
                ldm_x4(bf[jp], base + OFF_B + row * PITCH + cb);
            }
#pragma unroll
            for (int i = 0; i < 2; i++)
#pragma unroll
                for (int j = 0; j < 4; j++)
                    mma_fp16(acc[i][j], af[i], &bf[j >> 1][(j & 1) * 2]);
        }
    };

    // depth-1 prefetch, 2 buffers
    stage_load(0);
#pragma unroll 1
    for (int s = 0; s < S; s++) {
        if (s + 1 < S) {
            stage_load(s + 1);
            asm volatile("cp.async.wait_group 1;" ::: "memory");
        } else {
            asm volatile("cp.async.wait_group 0;" ::: "memory");
        }
        __syncthreads();
        compute(s);
        __syncthreads();
    }

    lstm_epilogue<0>(acc, row0, col0, g_b0, g_c0, hB);
}

// ---------------- gemm1: z=[h0_new|h1_prev]@W1'^T + b1 -> h1,c1 (K=512) ------
// B (W1 slice) is PERSISTENT in smem at WB; only A is staged per stage.
__device__ __forceinline__ void gemm1_tile(
    uint32_t AB, uint32_t WB, int row0, int col0,
    const __half* __restrict__ hA, __half* __restrict__ hB)
{
    constexpr int S = 8;
    const int tid = threadIdx.x;
    const int lane = tid & 31, warp = tid >> 5;
    const int wm = warp >> 2, wn = warp & 3;

    float acc[2][4][4];
#pragma unroll
    for (int i = 0; i < 2; i++)
#pragma unroll
        for (int j = 0; j < 4; j++)
#pragma unroll
            for (int r = 0; r < 4; r++) acc[i][j][r] = 0.f;

    auto stage_load = [&](int s) {
        const uint32_t bb = AB + (uint32_t)(s % 3) * A_STG;
        const __half* ah = (s < 4) ? hB : hA;   // [h0_new | h1_prev]
        const int koff = s * 64;
#pragma unroll
        for (int rr = 0; rr < 2; rr++) {
            int pos = rr * NTHREADS + tid;
            int row = pos >> 3, c = pos & 7;
            cp16(bb + row * PITCH + c * 16,
                 ah + (size_t)(row0 + row) * 512 + koff + c * 8);
        }
        asm volatile("cp.async.commit_group;");
    };

    auto compute = [&](int s) {
        const uint32_t base = AB + (uint32_t)(s % 3) * A_STG;
#pragma unroll
        for (int kk = 0; kk < 64; kk += 16) {
            uint32_t af[2][4], bf[2][4];
#pragma unroll
            for (int i = 0; i < 2; i++) {
                uint32_t row = wm * 32 + i * 16 + (lane & 15);
                uint32_t cb = (kk + ((lane >> 4) << 3)) * 2;
                ldm_x4(af[i], base + row * PITCH + cb);
            }
#pragma unroll
            for (int jp = 0; jp < 2; jp++) {
                uint32_t row = wn * 32 + jp * 16 + (lane & 7) + ((lane >> 4) << 3);
                uint32_t col = s * 64 + kk + (((lane >> 3) & 1) << 3);
                ldm_x4(bf[jp], WB + row * W1_PITCH + col * 2);
            }
#pragma unroll
            for (int i = 0; i < 2; i++)
#pragma unroll
                for (int j = 0; j < 4; j++)
                    mma_fp16(acc[i][j], af[i], &bf[j >> 1][(j & 1) * 2]);
        }
    };

    // depth-2 prefetch, 3 buffers (tiny 18KB A stages)
    stage_load(0);
    stage_load(1);
#pragma unroll 1
    for (int s = 0; s < S; s++) {
        if (s + 2 < S) {
            stage_load(s + 2);
            asm volatile("cp.async.wait_group 2;" ::: "memory");
        } else if (s + 1 < S) {
            asm volatile("cp.async.wait_group 1;" ::: "memory");
        } else {
            asm volatile("cp.async.wait_group 0;" ::: "memory");
        }
        __syncthreads();
        compute(s);
        __syncthreads();
    }

    lstm_epilogue<1>(acc, row0, col0, g_b1, g_c1, hB);
}

// ---------------- per-warp projection + softplus + CRPS (one batch row) ----
// Returns this row's CRPS contribution (same value in all lanes). NO atomics.
__device__ float proj_crps_row(int b, int t, const __half* __restrict__ hB,
                               const float* __restrict__ labels)
{
    const int lane = threadIdx.x & 31;
    const __half* hrow = hB + (size_t)b * 512;

    float hreg[16];
#pragma unroll
    for (int j = 0; j < 16; j++) hreg[j] = __half2float(hrow[lane + 32 * j]);

    float sp[21];
#pragma unroll 1
    for (int m = 0; m < 21; m++) {
        const float* wv = g_Wp + m * 512;
        float a = 0.f;
#pragma unroll
        for (int j = 0; j < 16; j++) a += hreg[j] * wv[lane + 32 * j];
#pragma unroll
        for (int o = 16; o; o >>= 1) a += __shfl_xor_sync(0xFFFFFFFFu, a, o);
        sp[m] = softplusf(a + g_pb[m]);   // all lanes hold the same value
    }

    const float invk = 1.0f / (float)KSEG;
    float beta0 = sp[0];
    float g[KSEG];
#pragma unroll
    for (int j = 0; j < KSEG; j++) g[j] = sp[1 + j];

    float braw[KSEG];
    braw[0] = (g[0] - beta0) * (0.5f * KSEG);
#pragma unroll
    for (int i = 1; i < KSEG; i++) braw[i] = (g[i] - g[i - 1]) * (0.5f * KSEG);
    float bb[KSEG];
    bb[0] = braw[0];
#pragma unroll
    for (int i = 1; i < KSEG; i++) bb[i] = braw[i] - braw[i - 1];
    float ssum = 0.f;
#pragma unroll
    for (int i = 0; i < KSEG - 1; i++) ssum += bb[i];
    bb[KSEG - 1] = g[KSEG - 1] - ssum;

    float F[KSEG];
    for (int i = 0; i < KSEG; i++) {
        float acc = (float)(i + 1) * invk * beta0;
        for (int j = 0; j <= i; j++) {
            float d = (float)(i + 1 - j) * invk;
            acc += d * d * bb[j];
        }
        F[i] = acc;
    }

    float y = labels[b * TT + t];
    float A = 0.f, Bc = beta0, C = -y;
    float mind = 1e30f; int amin = 0;
    unsigned almask = 0;
    for (int i = 0; i < KSEG; i++) {
        float knot = (i == 0) ? 0.f : F[i - 1];
        float diff = y - knot;
        float ad = fabsf(diff);
        if (ad < mind) { mind = ad; amin = i; }
        if (diff > 0.f) {
            almask |= (1u << i);
            float ksi = (float)i * invk;
            A += bb[i];
            Bc -= 2.f * bb[i] * ksi;
            C += bb[i] * ksi * ksi;
        }
    }
    float disc = Bc * Bc - 4.f * A * C;
    float alpha;
    if (A != 0.f && disc >= 0.f)       alpha = (-Bc + sqrtf(disc)) / (2.f * A);
    else if (A == 0.f)                 alpha = -C / ((Bc == 0.f) ? 1.f : Bc);
    else                               alpha = (float)amin * invk;

    float crps = -y * (1.f - 2.f * alpha) + beta0 * (1.f / 3.f - alpha * alpha);
    for (int i = 0; i < KSEG; i++) {
        float ksi = (float)i * invk;
        float om = 1.f - ksi;
        crps += bb[i] * (1.f / 6.f) * om * om * om * om;
        if ((almask >> i) & 1u) {
            float d = alpha - ksi;
            crps -= (2.f / 3.f) * bb[i] * d * d * d;
        }
    }
    return crps;
}

// ---------------- the persistent kernel: all 96 steps ----------------
__global__ void __launch_bounds__(NTHREADS)
lstm_persist(const float* __restrict__ labels, float* __restrict__ out)
{
    extern __shared__ float smraw[];
    const uint32_t AB = smem_u32(smraw);
    const uint32_t WB = AB + WB_OFF;
    const int ct = blockIdx.x & 7;        // col tile (128 gate cols)
    const int rt = blockIdx.x >> 3;       // row tile (128 batch rows)
    const int row0 = rt * 128;
    const int col0 = ct * 128;
    const int warp = threadIdx.x >> 5;
    const int pb = row0 + ct * 16 + warp; // one proj row per warp, inside own rt

    // load persistent W1 slice (128 rows x 512 k) once
    {
        const int tid = threadIdx.x;
#pragma unroll
        for (int i = 0; i < 16; i++) {
            int pos = i * NTHREADS + tid;
            int row = pos >> 6, c = pos & 63;
            cp16(WB + row * W1_PITCH + c * 16,
                 g_W1 + (size_t)(col0 + row) * 512 + c * 8);
        }
        asm volatile("cp.async.commit_group;");
        asm volatile("cp.async.wait_group 0;" ::: "memory");
        __syncthreads();
    }

    float crps_acc = 0.f;

#pragma unroll 1
    for (int t = 0; t < TT; t++) {
        const int rd = t & 1;
        const __half* hA = rd ? g_hb1 : g_hb0;    // previous-step state
        __half*       hB = rd ? g_hb0 : g_hb1;    // this-step state

        gemm0_tile(AB, row0, col0, t, hA, hB);
        grid_bar();                                // h0_new visible everywhere
        gemm1_tile(AB, WB, row0, col0, hA, hB);
        grid_bar();                                // h1_new visible everywhere
        crps_acc += proj_crps_row(pb, t, hB, labels);
    }

    if ((threadIdx.x & 31) == 0)
        atomicAdd(out, crps_acc * (1.0f / (float)BSZ));
}

// ---------------- host launch ----------------
extern "C" void kernel_launch(void* const* d_in, const int* in_sizes, int n_in,
                              void* d_out, int out_size)
{
    const float* train  = (const float*)d_in[0];
    const float* labels = (const float*)d_in[1];
    const float* Wih0 = (const float*)d_in[2];
    const float* Whh0 = (const float*)d_in[3];
    const float* Wih1 = (const float*)d_in[4];
    const float* Whh1 = (const float*)d_in[5];
    const float* bih0 = (const float*)d_in[6];
    const float* bhh0 = (const float*)d_in[7];
    const float* bih1 = (const float*)d_in[8];
    const float* bhh1 = (const float*)d_in[9];
    const float* Wpb  = (const float*)d_in[10];
    const float* bpb  = (const float*)d_in[11];
    const float* Wpg  = (const float*)d_in[12];
    const float* bpg  = (const float*)d_in[13];
    float* out = (float*)d_out;

    cudaFuncSetAttribute(lstm_persist, cudaFuncAttributeMaxDynamicSharedMemorySize, SMEM_REQ);

    zero_state<<<(BSZ * 512 + 255) / 256, 256>>>(out);
    presplit_x<<<(BSZ * TT * DIN + 255) / 256, 256>>>(train);
    build_weights<<<(1024 * 512 + 255) / 256, 256>>>(
        Wih0, Whh0, Wih1, Whh1, bih0, bhh0, bih1, bhh1, Wpb, bpb, Wpg, bpg);

    lstm_persist<<<NCTA, NTHREADS, SMEM_REQ>>>(labels, out);
}

// round 13
// speedup vs baseline: 1.2169x; 1.2169x over previous
#include <cuda_runtime.h>
#include <cuda_fp16.h>
#include <math.h>
#include <stdint.h>

// Problem constants
#define BSZ   2048
#define TT    96
#define DIN   64
#define HH    256
#define KSEG  20

#define NCTA     128
#define NTHREADS 512

// per-CTA tile: 128(M) x 128(N), BK=64 stages, 3-buffer depth-2 pipeline
#define PITCH   144                       // 128B data + 16B pad (conflict-free ldsm)
#define OFF_B   (128 * PITCH)             // 18432
#define STAGE_B (2 * 128 * PITCH)         // 36864
#define NBUF    3
#define SMEM_REQ (NBUF * STAGE_B + 64)    // ~108KB -> 1 CTA/SM, L1 stays ~120KB

// ---------------- device scratch ----------------
__device__ __half g_x[BSZ * TT * DIN];
__device__ __half g_W0[1024 * 320];   // gate-interleaved n'=4h+g, K-major
__device__ __half g_W1[1024 * 512];
__device__ float g_b0[1024];
__device__ float g_b1[1024];
__device__ float g_Wp[21 * 512];
__device__ float g_pb[21];
__device__ float g_c0[BSZ * HH];
__device__ float g_c1[BSZ * HH];
// 3-deep h rotation: h(t) lives in g_hb[t % 3]; [b][0:256]=h0, [256:512]=h1
__device__ __half g_hb[3][BSZ * 512];
// grid barrier state (monotone generation -> replay-safe)
__device__ unsigned g_count = 0;
__device__ unsigned g_gen   = 0;

// ---------------- helpers ----------------
__device__ __forceinline__ uint32_t smem_u32(const void* p) {
    uint32_t a;
    asm("{ .reg .u64 t; cvta.to.shared.u64 t, %1; cvt.u32.u64 %0, t; }" : "=r"(a) : "l"(p));
    return a;
}
__device__ __forceinline__ void cp16(uint32_t dst, const void* src) {
    asm volatile("cp.async.cg.shared.global [%0], [%1], 16;" :: "r"(dst), "l"(src));
}
__device__ __forceinline__ void ldm_x4(uint32_t* r, uint32_t addr) {
    asm volatile("ldmatrix.sync.aligned.m8n8.x4.shared.b16 {%0,%1,%2,%3}, [%4];"
        : "=r"(r[0]), "=r"(r[1]), "=r"(r[2]), "=r"(r[3]) : "r"(addr));
}
__device__ __forceinline__ void mma_fp16(float* d, const uint32_t* a, const uint32_t* b) {
    asm volatile(
        "mma.sync.aligned.m16n8k16.row.col.f32.f16.f16.f32 "
        "{%0,%1,%2,%3}, {%4,%5,%6,%7}, {%8,%9}, {%0,%1,%2,%3};"
        : "+f"(d[0]), "+f"(d[1]), "+f"(d[2]), "+f"(d[3])
        : "r"(a[0]), "r"(a[1]), "r"(a[2]), "r"(a[3]), "r"(b[0]), "r"(b[1]));
}
__device__ __forceinline__ float fsig(float x)  { return 1.f / (1.f + __expf(-x)); }
__device__ __forceinline__ float ftanh(float x) { return 2.f / (1.f + __expf(-2.f * x)) - 1.f; }
__device__ __forceinline__ float softplusf(float x) {
    return fmaxf(x, 0.f) + log1pf(expf(-fabsf(x)));
}

// grid-wide barrier: all NCTA CTAs resident by construction
__device__ __forceinline__ void grid_bar() {
    __syncthreads();
    if (threadIdx.x == 0) {
        unsigned my = *((volatile unsigned*)&g_gen);
        __threadfence();
        unsigned old = atomicAdd(&g_count, 1);
        if (old == NCTA - 1) {
            atomicExch(&g_count, 0);
            __threadfence();
            atomicAdd(&g_gen, 1);
        } else {
            while (*((volatile unsigned*)&g_gen) == my) __nanosleep(32);
        }
        __threadfence();
    }
    __syncthreads();
}

// ---------------- init kernels ----------------
__global__ void zero_state(float* out) {
    int i = blockIdx.x * blockDim.x + threadIdx.x;
    if (i < BSZ * 512) {
        __half z = __float2half(0.f);
        g_hb[0][i] = z; g_hb[1][i] = z; g_hb[2][i] = z;
    }
    if (i < BSZ * HH) { g_c0[i] = 0.f; g_c1[i] = 0.f; }
    if (i == 0) out[0] = 0.f;
}

__global__ void presplit_x(const float* __restrict__ train) {
    int i = blockIdx.x * blockDim.x + threadIdx.x;
    if (i < BSZ * TT * DIN) g_x[i] = __float2half(train[i]);
}

__global__ void build_weights(
    const float* __restrict__ Wih0, const float* __restrict__ Whh0,
    const float* __restrict__ Wih1, const float* __restrict__ Whh1,
    const float* __restrict__ bih0, const float* __restrict__ bhh0,
    const float* __restrict__ bih1, const float* __restrict__ bhh1,
    const float* __restrict__ Wpb,  const float* __restrict__ bpb,
    const float* __restrict__ Wpg,  const float* __restrict__ bpg)
{
    int i = blockIdx.x * blockDim.x + threadIdx.x;
    if (i < 1024 * 320) {
        int np = i / 320, k = i % 320;
        int n = (np & 3) * 256 + (np >> 2);               // gate-interleave
        float v = (k < 64) ? Wih0[n * 64 + k] : Whh0[n * 256 + (k - 64)];
        g_W0[i] = __float2half(v);
    }
    if (i < 1024 * 512) {
        int np = i / 512, k = i % 512;
        int n = (np & 3) * 256 + (np >> 2);
        float v = (k < 256) ? Wih1[n * 256 + k] : Whh1[n * 256 + (k - 256)];
        g_W1[i] = __float2half(v);
    }
    if (i < 21 * 512) {
        int m = i / 512, k = i % 512;
        int src = 2 * (k & 255) + (k >> 8);               // hp[2j+l] = hcat[j+256l]
        g_Wp[i] = (m == 0) ? Wpb[src] : Wpg[(m - 1) * 512 + src];
    }
    if (i < 1024) {
        int n = (i & 3) * 256 + (i >> 2);
        g_b0[i] = bih0[n] + bhh0[n];
        g_b1[i] = bih1[n] + bhh1[n];
    }
    if (i < 21) g_pb[i] = (i == 0) ? bpb[0] : bpg[i - 1];
}

// ---------------- fused fp16 mma GEMM tile + LSTM cell ----------------
// MODE 0: z = [x_t | h0_prev] @ W0'^T + b0 -> h0,c0   (K=320, 5 stages)
//         hA = h(t-1) buffer, hB = h(t) buffer
// MODE 1: z = [h0_new | h1_prev] @ W1'^T + b1 -> h1,c1 (K=512, 8 stages)
template <int MODE>
__device__ __forceinline__ void gemm_tile(
    uint32_t AB, int row0, int col0, int t,
    const __half* __restrict__ hA, __half* __restrict__ hB)
{
    constexpr int K = (MODE == 0) ? 320 : 512;
    constexpr int S = K / 64;
    const __half* __restrict__ W   = (MODE == 0) ? g_W0 : g_W1;
    const float* __restrict__ bias = (MODE == 0) ? g_b0 : g_b1;
    float* cbuf = (MODE == 0) ? g_c0 : g_c1;
    const __half* xp = g_x + t * 64;

    const int tid = threadIdx.x;
    const int lane = tid & 31, warp = tid >> 5;
    const int wm = warp >> 2;             // 0..3 (M, 32 rows each)
    const int wn = warp & 3;              // 0..3 (N, 32 cols each)
    const int g = lane >> 2, tq = lane & 3;

    float acc[2][4][4];
#pragma unroll
    for (int i = 0; i < 2; i++)
#pragma unroll
        for (int j = 0; j < 4; j++)
#pragma unroll
            for (int r = 0; r < 4; r++) acc[i][j][r] = 0.f;

    // ---- stage loader: one BK=64 chunk into buffer (s % 3) ----
    auto stage_load = [&](int s) {
        const uint32_t bb = AB + (uint32_t)(s % 3) * STAGE_B;
        const __half* ah;
        int lda, koff;
        if (MODE == 0) {
            if (s == 0) { ah = xp; lda = TT * DIN; koff = 0; }
            else        { ah = hA; lda = 512;      koff = (s - 1) * 64; }
        } else {
            ah = (s < 4) ? hB : hA;   // [h0_new | h1_prev]
            lda = 512; koff = s * 64;
        }
        // A: 128 rows x 8 x 16B = 1024 chunks (2/thread)
#pragma unroll
        for (int rr = 0; rr < 2; rr++) {
            int pos = rr * NTHREADS + tid;
            int row = pos >> 3, c = pos & 7;
            cp16(bb + row * PITCH + c * 16,
                 ah + (size_t)(row0 + row) * lda + koff + c * 8);
        }
        // B: 128 rows x 8 x 16B = 1024 chunks (2/thread)
#pragma unroll
        for (int rr = 0; rr < 2; rr++) {
            int pos = rr * NTHREADS + tid;
            int row = pos >> 3, c = pos & 7;
            cp16(bb + OFF_B + row * PITCH + c * 16,
                 W + (size_t)(col0 + row) * K + s * 64 + c * 8);
        }
        asm volatile("cp.async.commit_group;");
    };

    // ---- compute one staged BK=64 chunk ----
    auto compute = [&](int s) {
        const uint32_t base = AB + (uint32_t)(s % 3) * STAGE_B;
#pragma unroll
        for (int kk = 0; kk < 64; kk += 16) {
            uint32_t af[2][4], bf[2][4];
#pragma unroll
            for (int i = 0; i < 2; i++) {
                uint32_t row = wm * 32 + i * 16 + (lane & 15);
                uint32_t cb = (kk + ((lane >> 4) << 3)) * 2;
                ldm_x4(af[i], base + row * PITCH + cb);
            }
#pragma unroll
            for (int jp = 0; jp < 2; jp++) {
                uint32_t row = wn * 32 + jp * 16 + (lane & 7) + ((lane >> 4) << 3);
                uint32_t cb = (kk + (((lane >> 3) & 1) << 3)) * 2;
                ldm_x4(bf[jp], base + OFF_B + row * PITCH + cb);
            }
#pragma unroll
            for (int i = 0; i < 2; i++)
#pragma unroll
                for (int j = 0; j < 4; j++)
                    mma_fp16(acc[i][j], af[i], &bf[j >> 1][(j & 1) * 2]);
        }
    };

    // ---- depth-2 pipeline, 3 buffers, 2 syncs per stage (R9 proven) ----
    stage_load(0);
    stage_load(1);
#pragma unroll 1
    for (int s = 0; s < S; s++) {
        if (s + 2 < S) {
            stage_load(s + 2);
            asm volatile("cp.async.wait_group 2;" ::: "memory");
        } else if (s + 1 < S) {
            asm volatile("cp.async.wait_group 1;" ::: "memory");
        } else {
            asm volatile("cp.async.wait_group 0;" ::: "memory");
        }
        __syncthreads();
        compute(s);
        __syncthreads();
    }

    // ---- fused LSTM epilogue ----
    // acc[i][j]: c0,c1=(m=g, n=2t,2t+1), c2,c3=(m=g+8, same n) at
    // (m = wm*32+i*16, n' = wn*32+j*8). lane^1 shuffle reassembles gate quads.
    const bool ev = (tq & 1) == 0;
    const int mrow = row0 + wm * 32 + g + (ev ? 0 : 8);
    __half* hout = hB + (MODE == 0 ? 0 : 256);
#pragma unroll
    for (int i = 0; i < 2; i++) {
        const int m = mrow + i * 16;
#pragma unroll
        for (int j = 0; j < 4; j++) {
            float* a = acc[i][j];
            float s0 = ev ? a[2] : a[0];
            float s1 = ev ? a[3] : a[1];
            float r0 = __shfl_xor_sync(0xFFFFFFFFu, s0, 1);
            float r1 = __shfl_xor_sync(0xFFFFFFFFu, s1, 1);
            float zi = ev ? a[0] : r0;
            float zf = ev ? a[1] : r1;
            float zg = ev ? r0 : a[2];
            float zo = ev ? r1 : a[3];
            int ul = wn * 8 + j * 2 + (tq >> 1);
            float4 bz = *(const float4*)(bias + col0 + 4 * ul);
            int ug = (col0 >> 2) + ul;
            zi += bz.x; zf += bz.y; zg += bz.z; zo += bz.w;
            float cold = cbuf[(size_t)m * HH + ug];
            float c2 = fsig(zf) * cold + fsig(zi) * ftanh(zg);
            float hv = fsig(zo) * ftanh(c2);
            cbuf[(size_t)m * HH + ug] = c2;
            hout[(size_t)m * 512 + ug] = __float2half(hv);
        }
    }
}

// ---------------- per-warp projection + softplus + CRPS (one batch row) ----
// Returns this row's CRPS contribution (same value in all lanes). NO atomics.
__device__ float proj_crps_row(int b, int t, const __half* __restrict__ hB,
                               const float* __restrict__ labels)
{
    const int lane = threadIdx.x & 31;
    const __half* hrow = hB + (size_t)b * 512;

    float hreg[16];
#pragma unroll
    for (int j = 0; j < 16; j++) hreg[j] = __half2float(hrow[lane + 32 * j]);

    float sp[21];
#pragma unroll 1
    for (int m = 0; m < 21; m++) {
        const float* wv = g_Wp + m * 512;
        float a = 0.f;
#pragma unroll
        for (int j = 0; j < 16; j++) a += hreg[j] * wv[lane + 32 * j];
#pragma unroll
        for (int o = 16; o; o >>= 1) a += __shfl_xor_sync(0xFFFFFFFFu, a, o);
        sp[m] = softplusf(a + g_pb[m]);   // all lanes hold the same value
    }

    const float invk = 1.0f / (float)KSEG;
    float beta0 = sp[0];
    float g[KSEG];
#pragma unroll
    for (int j = 0; j < KSEG; j++) g[j] = sp[1 + j];

    float braw[KSEG];
    braw[0] = (g[0] - beta0) * (0.5f * KSEG);
#pragma unroll
    for (int i = 1; i < KSEG; i++) braw[i] = (g[i] - g[i - 1]) * (0.5f * KSEG);
    float bb[KSEG];
    bb[0] = braw[0];
#pragma unroll
    for (int i = 1; i < KSEG; i++) bb[i] = braw[i] - braw[i - 1];
    float ssum = 0.f;
#pragma unroll
    for (int i = 0; i < KSEG - 1; i++) ssum += bb[i];
    bb[KSEG - 1] = g[KSEG - 1] - ssum;

    float F[KSEG];
    for (int i = 0; i < KSEG; i++) {
        float acc = (float)(i + 1) * invk * beta0;
        for (int j = 0; j <= i; j++) {
            float d = (float)(i + 1 - j) * invk;
            acc += d * d * bb[j];
        }
        F[i] = acc;
    }

    float y = labels[b * TT + t];
    float A = 0.f, Bc = beta0, C = -y;
    float mind = 1e30f; int amin = 0;
    unsigned almask = 0;
    for (int i = 0; i < KSEG; i++) {
        float knot = (i == 0) ? 0.f : F[i - 1];
        float diff = y - knot;
        float ad = fabsf(diff);
        if (ad < mind) { mind = ad; amin = i; }
        if (diff > 0.f) {
            almask |= (1u << i);
            float ksi = (float)i * invk;
            A += bb[i];
            Bc -= 2.f * bb[i] * ksi;
            C += bb[i] * ksi * ksi;
        }
    }
    float disc = Bc * Bc - 4.f * A * C;
    float alpha;
    if (A != 0.f && disc >= 0.f)       alpha = (-Bc + sqrtf(disc)) / (2.f * A);
    else if (A == 0.f)                 alpha = -C / ((Bc == 0.f) ? 1.f : Bc);
    else                               alpha = (float)amin * invk;

    float crps = -y * (1.f - 2.f * alpha) + beta0 * (1.f / 3.f - alpha * alpha);
    for (int i = 0; i < KSEG; i++) {
        float ksi = (float)i * invk;
        float om = 1.f - ksi;
        crps += bb[i] * (1.f / 6.f) * om * om * om * om;
        if ((almask >> i) & 1u) {
            float d = alpha - ksi;
            crps -= (2.f / 3.f) * bb[i] * d * d * d;
        }
    }
    return crps;
}

// ---------------- the persistent kernel: all 96 steps, ONE bar/step --------
// h(t) lives in g_hb[t%3]. Phase t (between bars) = { gemm1(t), gemm0(t+1) }:
// both depend only on h0(t) (bar before). proj(t) runs after the bar ending
// phase t; concurrent phase-(t+1) writers touch g_hb[(t+1)%3] / g_hb[(t+2)%3],
// never g_hb[t%3], so proj reads are race-free.
__global__ void __launch_bounds__(NTHREADS)
lstm_persist(const float* __restrict__ labels, float* __restrict__ out)
{
    extern __shared__ float smraw[];
    const uint32_t AB = smem_u32(smraw);
    const int ct = blockIdx.x & 7;        // col tile (128 gate cols)
    const int rt = blockIdx.x >> 3;       // row tile (128 batch rows)
    const int row0 = rt * 128;
    const int col0 = ct * 128;
    const int warp = threadIdx.x >> 5;
    const int pb = row0 + ct * 16 + warp; // one proj row per warp, inside own rt

    float crps_acc = 0.f;

    // step 0 layer 0: h(-1) = g_hb[2] (zeroed)
    gemm_tile<0>(AB, row0, col0, 0, g_hb[2], g_hb[0]);
    grid_bar();

#pragma unroll 1
    for (int t = 0; t < TT; t++) {
        const __half* hprev = g_hb[(t + 2) % 3];   // h(t-1)
        __half*       hcur  = g_hb[t % 3];         // h(t)
        __half*       hnext = g_hb[(t + 1) % 3];   // h(t+1)

        gemm_tile<1>(AB, row0, col0, t, hprev, hcur);      // h1(t), c1
        if (t + 1 < TT)
            gemm_tile<0>(AB, row0, col0, t + 1, hcur, hnext); // h0(t+1), c0
        grid_bar();
        crps_acc += proj_crps_row(pb, t, hcur, labels);
    }

    if ((threadIdx.x & 31) == 0)
        atomicAdd(out, crps_acc * (1.0f / (float)BSZ));
}

// ---------------- host launch ----------------
extern "C" void kernel_launch(void* const* d_in, const int* in_sizes, int n_in,
                              void* d_out, int out_size)
{
    const float* train  = (const float*)d_in[0];
    const float* labels = (const float*)d_in[1];
    const float* Wih0 = (const float*)d_in[2];
    const float* Whh0 = (const float*)d_in[3];
    const float* Wih1 = (const float*)d_in[4];
    const float* Whh1 = (const float*)d_in[5];
    const float* bih0 = (const float*)d_in[6];
    const float* bhh0 = (const float*)d_in[7];
    const float* bih1 = (const float*)d_in[8];
    const float* bhh1 = (const float*)d_in[9];
    const float* Wpb  = (const float*)d_in[10];
    const float* bpb  = (const float*)d_in[11];
    const float* Wpg  = (const float*)d_in[12];
    const float* bpg  = (const float*)d_in[13];
    float* out = (float*)d_out;

    cudaFuncSetAttribute(lstm_persist, cudaFuncAttributeMaxDynamicSharedMemorySize, SMEM_REQ);

    zero_state<<<(BSZ * 512 + 255) / 256, 256>>>(out);
    presplit_x<<<(BSZ * TT * DIN + 255) / 256, 256>>>(train);
    build_weights<<<(1024 * 512 + 255) / 256, 256>>>(
        Wih0, Whh0, Wih1, Whh1, bih0, bhh0, bih1, bhh1, Wpb, bpb, Wpg, bpg);

    lstm_persist<<<NCTA, NTHREADS, SMEM_REQ>>>(labels, out);
}

// round 14
// speedup vs baseline: 1.7552x; 1.4423x over previous
#include <cuda_runtime.h>
#include <cuda_fp16.h>
#include <math.h>
#include <stdint.h>

// Problem constants
#define BSZ   2048
#define TT    96
#define DIN   64
#define HH    256
#define KSEG  20

#define NCTA     128
#define NTHREADS 1024

// per-CTA tile: 128(M) x 128(N), BK=64 stages, 3-buffer depth-2 pipeline
#define PITCH   144                       // 128B data + 16B pad (conflict-free ldsm)
#define OFF_B   (128 * PITCH)             // 18432
#define STAGE_B (2 * 128 * PITCH)         // 36864
#define NBUF    3
#define SMEM_REQ (NBUF * STAGE_B + 64)    // ~108KB -> 1 CTA/SM, L1 stays ~120KB

// ---------------- device scratch ----------------
__device__ __half g_x[BSZ * TT * DIN];
__device__ __half g_W0[1024 * 320];   // gate-interleaved n'=4h+g, K-major
__device__ __half g_W1[1024 * 512];
__device__ float g_b0[1024];
__device__ float g_b1[1024];
__device__ float g_Wp[21 * 512];
__device__ float g_pb[21];
__device__ float g_c0[BSZ * HH];
__device__ float g_c1[BSZ * HH];
// 3-deep h rotation: h(t) lives in g_hb[t % 3]; [b][0:256]=h0, [256:512]=h1
__device__ __half g_hb[3][BSZ * 512];
// grid barrier state (monotone generation -> replay-safe)
__device__ unsigned g_count = 0;
__device__ unsigned g_gen   = 0;

// ---------------- helpers ----------------
__device__ __forceinline__ uint32_t smem_u32(const void* p) {
    uint32_t a;
    asm("{ .reg .u64 t; cvta.to.shared.u64 t, %1; cvt.u32.u64 %0, t; }" : "=r"(a) : "l"(p));
    return a;
}
__device__ __forceinline__ void cp16(uint32_t dst, const void* src) {
    asm volatile("cp.async.cg.shared.global [%0], [%1], 16;" :: "r"(dst), "l"(src));
}
__device__ __forceinline__ void ldm_x4(uint32_t* r, uint32_t addr) {
    asm volatile("ldmatrix.sync.aligned.m8n8.x4.shared.b16 {%0,%1,%2,%3}, [%4];"
        : "=r"(r[0]), "=r"(r[1]), "=r"(r[2]), "=r"(r[3]) : "r"(addr));
}
__device__ __forceinline__ void mma_fp16(float* d, const uint32_t* a, const uint32_t* b) {
    asm volatile(
        "mma.sync.aligned.m16n8k16.row.col.f32.f16.f16.f32 "
        "{%0,%1,%2,%3}, {%4,%5,%6,%7}, {%8,%9}, {%0,%1,%2,%3};"
        : "+f"(d[0]), "+f"(d[1]), "+f"(d[2]), "+f"(d[3])
        : "r"(a[0]), "r"(a[1]), "r"(a[2]), "r"(a[3]), "r"(b[0]), "r"(b[1]));
}
__device__ __forceinline__ float fsig(float x)  { return 1.f / (1.f + __expf(-x)); }
__device__ __forceinline__ float ftanh(float x) { return 2.f / (1.f + __expf(-2.f * x)) - 1.f; }
__device__ __forceinline__ float softplusf(float x) {
    return fmaxf(x, 0.f) + log1pf(expf(-fabsf(x)));
}

// grid-wide barrier: all NCTA CTAs resident by construction
__device__ __forceinline__ void grid_bar() {
    __syncthreads();
    if (threadIdx.x == 0) {
        unsigned my = *((volatile unsigned*)&g_gen);
        __threadfence();
        unsigned old = atomicAdd(&g_count, 1);
        if (old == NCTA - 1) {
            atomicExch(&g_count, 0);
            __threadfence();
            atomicAdd(&g_gen, 1);
        } else {
            while (*((volatile unsigned*)&g_gen) == my) __nanosleep(32);
        }
        __threadfence();
    }
    __syncthreads();
}

// ---------------- init kernels ----------------
__global__ void zero_state(float* out) {
    int i = blockIdx.x * blockDim.x + threadIdx.x;
    if (i < BSZ * 512) {
        __half z = __float2half(0.f);
        g_hb[0][i] = z; g_hb[1][i] = z; g_hb[2][i] = z;
    }
    if (i < BSZ * HH) { g_c0[i] = 0.f; g_c1[i] = 0.f; }
    if (i == 0) out[0] = 0.f;
}

__global__ void presplit_x(const float* __restrict__ train) {
    int i = blockIdx.x * blockDim.x + threadIdx.x;
    if (i < BSZ * TT * DIN) g_x[i] = __float2half(train[i]);
}

__global__ void build_weights(
    const float* __restrict__ Wih0, const float* __restrict__ Whh0,
    const float* __restrict__ Wih1, const float* __restrict__ Whh1,
    const float* __restrict__ bih0, const float* __restrict__ bhh0,
    const float* __restrict__ bih1, const float* __restrict__ bhh1,
    const float* __restrict__ Wpb,  const float* __restrict__ bpb,
    const float* __restrict__ Wpg,  const float* __restrict__ bpg)
{
    int i = blockIdx.x * blockDim.x + threadIdx.x;
    if (i < 1024 * 320) {
        int np = i / 320, k = i % 320;
        int n = (np & 3) * 256 + (np >> 2);               // gate-interleave
        float v = (k < 64) ? Wih0[n * 64 + k] : Whh0[n * 256 + (k - 64)];
        g_W0[i] = __float2half(v);
    }
    if (i < 1024 * 512) {
        int np = i / 512, k = i % 512;
        int n = (np & 3) * 256 + (np >> 2);
        float v = (k < 256) ? Wih1[n * 256 + k] : Whh1[n * 256 + (k - 256)];
        g_W1[i] = __float2half(v);
    }
    if (i < 21 * 512) {
        int m = i / 512, k = i % 512;
        int src = 2 * (k & 255) + (k >> 8);               // hp[2j+l] = hcat[j+256l]
        g_Wp[i] = (m == 0) ? Wpb[src] : Wpg[(m - 1) * 512 + src];
    }
    if (i < 1024) {
        int n = (i & 3) * 256 + (i >> 2);
        g_b0[i] = bih0[n] + bhh0[n];
        g_b1[i] = bih1[n] + bhh1[n];
    }
    if (i < 21) g_pb[i] = (i == 0) ? bpb[0] : bpg[i - 1];
}

// ---------------- fused fp16 mma GEMM tile + LSTM cell ----------------
// 32 warps: wm=warp>>2 (0..7, 16 rows), wn=warp&3 (0..3, 32 cols)
// MODE 0: z = [x_t | h0_prev] @ W0'^T + b0 -> h0,c0   (K=320, 5 stages)
// MODE 1: z = [h0_new | h1_prev] @ W1'^T + b1 -> h1,c1 (K=512, 8 stages)
template <int MODE>
__device__ __forceinline__ void gemm_tile(
    uint32_t AB, int row0, int col0, int t,
    const __half* __restrict__ hA, __half* __restrict__ hB)
{
    constexpr int K = (MODE == 0) ? 320 : 512;
    constexpr int S = K / 64;
    const __half* __restrict__ W   = (MODE == 0) ? g_W0 : g_W1;
    const float* __restrict__ bias = (MODE == 0) ? g_b0 : g_b1;
    float* cbuf = (MODE == 0) ? g_c0 : g_c1;
    const __half* xp = g_x + t * 64;

    const int tid = threadIdx.x;
    const int lane = tid & 31, warp = tid >> 5;
    const int wm = warp >> 2;             // 0..7 (M, 16 rows each)
    const int wn = warp & 3;              // 0..3 (N, 32 cols each)
    const int g = lane >> 2, tq = lane & 3;

    float acc[4][4];
#pragma unroll
    for (int j = 0; j < 4; j++)
#pragma unroll
        for (int r = 0; r < 4; r++) acc[j][r] = 0.f;

    // ---- stage loader: one BK=64 chunk into buffer (s % 3) ----
    auto stage_load = [&](int s) {
        const uint32_t bb = AB + (uint32_t)(s % 3) * STAGE_B;
        const __half* ah;
        int lda, koff;
        if (MODE == 0) {
            if (s == 0) { ah = xp; lda = TT * DIN; koff = 0; }
            else        { ah = hA; lda = 512;      koff = (s - 1) * 64; }
        } else {
            ah = (s < 4) ? hB : hA;   // [h0_new | h1_prev]
            lda = 512; koff = s * 64;
        }
        // A: 128 rows x 8 x 16B = 1024 chunks (1/thread)
        {
            int row = tid >> 3, c = tid & 7;
            cp16(bb + row * PITCH + c * 16,
                 ah + (size_t)(row0 + row) * lda + koff + c * 8);
        }
        // B: 128 rows x 8 x 16B = 1024 chunks (1/thread)
        {
            int row = tid >> 3, c = tid & 7;
            cp16(bb + OFF_B + row * PITCH + c * 16,
                 W + (size_t)(col0 + row) * K + s * 64 + c * 8);
        }
        asm volatile("cp.async.commit_group;");
    };

    // ---- compute one staged BK=64 chunk ----
    auto compute = [&](int s) {
        const uint32_t base = AB + (uint32_t)(s % 3) * STAGE_B;
#pragma unroll
        for (int kk = 0; kk < 64; kk += 16) {
            uint32_t af[4], bf[2][4];
            {
                uint32_t row = wm * 16 + (lane & 15);
                uint32_t cb = (kk + ((lane >> 4) << 3)) * 2;
                ldm_x4(af, base + row * PITCH + cb);
            }
#pragma unroll
            for (int jp = 0; jp < 2; jp++) {
                uint32_t row = wn * 32 + jp * 16 + (lane & 7) + ((lane >> 4) << 3);
                uint32_t cb = (kk + (((lane >> 3) & 1) << 3)) * 2;
                ldm_x4(bf[jp], base + OFF_B + row * PITCH + cb);
            }
#pragma unroll
            for (int j = 0; j < 4; j++)
                mma_fp16(acc[j], af, &bf[j >> 1][(j & 1) * 2]);
        }
    };

    // ---- depth-2 pipeline, 3 buffers ----
    stage_load(0);
    stage_load(1);
#pragma unroll 1
    for (int s = 0; s < S; s++) {
        if (s + 2 < S) {
            stage_load(s + 2);
            asm volatile("cp.async.wait_group 2;" ::: "memory");
        } else if (s + 1 < S) {
            asm volatile("cp.async.wait_group 1;" ::: "memory");
        } else {
            asm volatile("cp.async.wait_group 0;" ::: "memory");
        }
        __syncthreads();
        compute(s);
        __syncthreads();
    }

    // ---- fused LSTM epilogue ----
    // acc[j]: c0,c1=(m=g, n=2t,2t+1), c2,c3=(m=g+8, same n) at
    // (m = wm*16, n' = wn*32+j*8). lane^1 shuffle reassembles gate quads.
    const bool ev = (tq & 1) == 0;
    const int m = row0 + wm * 16 + g + (ev ? 0 : 8);
    __half* hout = hB + (MODE == 0 ? 0 : 256);
#pragma unroll
    for (int j = 0; j < 4; j++) {
        float* a = acc[j];
        float s0 = ev ? a[2] : a[0];
        float s1 = ev ? a[3] : a[1];
        float r0 = __shfl_xor_sync(0xFFFFFFFFu, s0, 1);
        float r1 = __shfl_xor_sync(0xFFFFFFFFu, s1, 1);
        float zi = ev ? a[0] : r0;
        float zf = ev ? a[1] : r1;
        float zg = ev ? r0 : a[2];
        float zo = ev ? r1 : a[3];
        int ul = wn * 8 + j * 2 + (tq >> 1);
        float4 bz = *(const float4*)(bias + col0 + 4 * ul);
        int ug = (col0 >> 2) + ul;
        zi += bz.x; zf += bz.y; zg += bz.z; zo += bz.w;
        float cold = cbuf[(size_t)m * HH + ug];
        float c2 = fsig(zf) * cold + fsig(zi) * ftanh(zg);
        float hv = fsig(zo) * ftanh(c2);
        cbuf[(size_t)m * HH + ug] = c2;
        hout[(size_t)m * 512 + ug] = __float2half(hv);
    }
}

// ---------------- per-warp projection + softplus + CRPS (one batch row) ----
// Returns this row's CRPS contribution (same value in all lanes). NO atomics.
__device__ float proj_crps_row(int b, int t, const __half* __restrict__ hB,
                               const float* __restrict__ labels)
{
    const int lane = threadIdx.x & 31;
    const __half* hrow = hB + (size_t)b * 512;

    float hreg[16];
#pragma unroll
    for (int j = 0; j < 16; j++) hreg[j] = __half2float(hrow[lane + 32 * j]);

    float sp[21];
#pragma unroll 1
    for (int m = 0; m < 21; m++) {
        const float* wv = g_Wp + m * 512;
        float a = 0.f;
#pragma unroll
        for (int j = 0; j < 16; j++) a += hreg[j] * wv[lane + 32 * j];
#pragma unroll
        for (int o = 16; o; o >>= 1) a += __shfl_xor_sync(0xFFFFFFFFu, a, o);
        sp[m] = softplusf(a + g_pb[m]);   // all lanes hold the same value
    }

    const float invk = 1.0f / (float)KSEG;
    float beta0 = sp[0];
    float g[KSEG];
#pragma unroll
    for (int j = 0; j < KSEG; j++) g[j] = sp[1 + j];

    float braw[KSEG];
    braw[0] = (g[0] - beta0) * (0.5f * KSEG);
#pragma unroll
    for (int i = 1; i < KSEG; i++) braw[i] = (g[i] - g[i - 1]) * (0.5f * KSEG);
    float bb[KSEG];
    bb[0] = braw[0];
#pragma unroll
    for (int i = 1; i < KSEG; i++) bb[i] = braw[i] - braw[i - 1];
    float ssum = 0.f;
#pragma unroll
    for (int i = 0; i < KSEG - 1; i++) ssum += bb[i];
    bb[KSEG - 1] = g[KSEG - 1] - ssum;

    float F[KSEG];
    for (int i = 0; i < KSEG; i++) {
        float acc = (float)(i + 1) * invk * beta0;
        for (int j = 0; j <= i; j++) {
            float d = (float)(i + 1 - j) * invk;
            acc += d * d * bb[j];
        }
        F[i] = acc;
    }

    float y = labels[b * TT + t];
    float A = 0.f, Bc = beta0, C = -y;
    float mind = 1e30f; int amin = 0;
    unsigned almask = 0;
    for (int i = 0; i < KSEG; i++) {
        float knot = (i == 0) ? 0.f : F[i - 1];
        float diff = y - knot;
        float ad = fabsf(diff);
        if (ad < mind) { mind = ad; amin = i; }
        if (diff > 0.f) {
            almask |= (1u << i);
            float ksi = (float)i * invk;
            A += bb[i];
            Bc -= 2.f * bb[i] * ksi;
            C += bb[i] * ksi * ksi;
        }
    }
    float disc = Bc * Bc - 4.f * A * C;
    float alpha;
    if (A != 0.f && disc >= 0.f)       alpha = (-Bc + sqrtf(disc)) / (2.f * A);
    else if (A == 0.f)                 alpha = -C / ((Bc == 0.f) ? 1.f : Bc);
    else                               alpha = (float)amin * invk;

    float crps = -y * (1.f - 2.f * alpha) + beta0 * (1.f / 3.f - alpha * alpha);
    for (int i = 0; i < KSEG; i++) {
        float ksi = (float)i * invk;
        float om = 1.f - ksi;
        crps += bb[i] * (1.f / 6.f) * om * om * om * om;
        if ((almask >> i) & 1u) {
            float d = alpha - ksi;
            crps -= (2.f / 3.f) * bb[i] * d * d * d;
        }
    }
    return crps;
}

// ---------------- the persistent kernel: all 96 steps, ONE bar/step --------
// h(t) lives in g_hb[t%3]. Phase t (between bars) = { gemm1(t), gemm0(t+1) }:
// both depend only on h0(t) (bar before). proj(t) runs after the bar ending
// phase t; concurrent phase-(t+1) writers touch g_hb[(t+1)%3] / g_hb[(t+2)%3],
// never g_hb[t%3], so proj reads are race-free.
__global__ void __launch_bounds__(NTHREADS, 1)
lstm_persist(const float* __restrict__ labels, float* __restrict__ out)
{
    extern __shared__ float smraw[];
    const uint32_t AB = smem_u32(smraw);
    const int ct = blockIdx.x & 7;        // col tile (128 gate cols)
    const int rt = blockIdx.x >> 3;       // row tile (128 batch rows)
    const int row0 = rt * 128;
    const int col0 = ct * 128;
    const int warp = threadIdx.x >> 5;
    const bool do_proj = warp < 16;       // 16 proj warps x 128 CTAs = 2048 rows
    const int pb = row0 + ct * 16 + (warp & 15);

    float crps_acc = 0.f;

    // step 0 layer 0: h(-1) = g_hb[2] (zeroed)
    gemm_tile<0>(AB, row0, col0, 0, g_hb[2], g_hb[0]);
    grid_bar();

#pragma unroll 1
    for (int t = 0; t < TT; t++) {
        const __half* hprev = g_hb[(t + 2) % 3];   // h(t-1)
        __half*       hcur  = g_hb[t % 3];         // h(t)
        __half*       hnext = g_hb[(t + 1) % 3];   // h(t+1)

        gemm_tile<1>(AB, row0, col0, t, hprev, hcur);      // h1(t), c1
        if (t + 1 < TT)
            gemm_tile<0>(AB, row0, col0, t + 1, hcur, hnext); // h0(t+1), c0
        grid_bar();
        if (do_proj)
            crps_acc += proj_crps_row(pb, t, hcur, labels);
    }

    if (do_proj && (threadIdx.x & 31) == 0)
        atomicAdd(out, crps_acc * (1.0f / (float)BSZ));
}

// ---------------- host launch ----------------
extern "C" void kernel_launch(void* const* d_in, const int* in_sizes, int n_in,
                              void* d_out, int out_size)
{
    const float* train  = (const float*)d_in[0];
    const float* labels = (const float*)d_in[1];
    const float* Wih0 = (const float*)d_in[2];
    const float* Whh0 = (const float*)d_in[3];
    const float* Wih1 = (const float*)d_in[4];
    const float* Whh1 = (const float*)d_in[5];
    const float* bih0 = (const float*)d_in[6];
    const float* bhh0 = (const float*)d_in[7];
    const float* bih1 = (const float*)d_in[8];
    const float* bhh1 = (const float*)d_in[9];
    const float* Wpb  = (const float*)d_in[10];
    const float* bpb  = (const float*)d_in[11];
    const float* Wpg  = (const float*)d_in[12];
    const float* bpg  = (const float*)d_in[13];
    float* out = (float*)d_out;

    cudaFuncSetAttribute(lstm_persist, cudaFuncAttributeMaxDynamicSharedMemorySize, SMEM_REQ);

    zero_state<<<(BSZ * 512 + 255) / 256, 256>>>(out);
    presplit_x<<<(BSZ * TT * DIN + 255) / 256, 256>>>(train);
    build_weights<<<(1024 * 512 + 255) / 256, 256>>>(
        Wih0, Whh0, Wih1, Whh1, bih0, bhh0, bih1, bhh1, Wpb, bpb, Wpg, bpg);

    lstm_persist<<<NCTA, NTHREADS, SMEM_REQ>>>(labels, out);
}